// round 12
// baseline (speedup 1.0000x reference)
#include <cuda_runtime.h>
#include <stdint.h>
#include <stddef.h>

// ---------------------------------------------------------------------------
// MeshMultiHeadHodgeAttentionVertices — fp32 exact implementation
//
// Shapes: B=2, N=4096, M=12288, H=8, D=256 (dk=32), KV=KE=16
// Layout convention: every activation is (batch, rows, 256) row-major with
// column c = h*32 + d  (== split_heads column block). This makes LayerNorm
// (per 32-col block), sparse attention (per 32-col block) and the final
// transpose+reshape all trivial.
//
// Pipeline:
//   1) vQ,vK,vV = x_v @ W^T   (GEMM, TB)     rows = B*N = 8192
//      eQ,eK    = x_e @ W^T   (GEMM, TB)     rows = B*M = 24576
//   2) LayerNorm(32) in-place on vQ,vK,eQ,eK
//   3) y1[b] = d0[b] @ vV[b]                 (GEMM NN, K=4096)
//   4) y2 = sparse_attn(q=eQ, k=eK, v=y1, e_idx)
//   5) z1[b] = d0[b]^T @ y2[b]               (GEMM TA, K=12288)
//   6) out = sparse_attn(q=vK, k=vQ, v=z1, v_idx)
//
// GEMM core: 128x128x8 tile, 256 threads, 8x8 per thread, accumulation via
// packed fma.rn.f32x2 (FFMA2) -> 2x the fp32 FFMA rate on sm_103a.
// ---------------------------------------------------------------------------

#define B_SZ 2
#define N_SZ 4096
#define M_SZ 12288
#define D_SZ 256

// scratch offsets (floats)
#define OFF_VQ 0ull
#define OFF_VK 2097152ull       //  B*N*256
#define OFF_VV 4194304ull
#define OFF_EQ 6291456ull       //  then B*M*256 blocks
#define OFF_EK 12582912ull
#define OFF_Y1 18874368ull
#define OFF_Y2 25165824ull
#define OFF_Z1 31457280ull
#define SCRATCH_FLOATS 33554432ull   // 128 MiB

__device__ float g_scratch[SCRATCH_FLOATS];

// ---- packed fp32x2 helpers (sm_103a FFMA2 via PTX) ------------------------
__device__ __forceinline__ unsigned long long splat2(float a) {
    unsigned int u = __float_as_uint(a);
    unsigned long long r;
    asm("mov.b64 %0, {%1, %1};" : "=l"(r) : "r"(u));
    return r;
}
__device__ __forceinline__ unsigned long long ffma2(unsigned long long a,
                                                    unsigned long long b,
                                                    unsigned long long c) {
    unsigned long long d;
    asm("fma.rn.f32x2 %0, %1, %2, %3;" : "=l"(d) : "l"(a), "l"(b), "l"(c));
    return d;
}

// ---------------------------------------------------------------------------
// Tiled GEMM:  C[i,j] = sum_k Aop[i,k] * Bop[k,j]
//   TA=false: A row-major (i,k), lda = row stride
//   TA=true : A stored (k,i), lda = stride per k  (i.e. C = A^T_storage @ B)
//   TB=false: B row-major (k,j), ldb = row stride
//   TB=true : B stored (j,k), ldb = row stride    (i.e. B = W^T)
// All dims must be multiples of the tile (they are, by construction).
// ---------------------------------------------------------------------------
template <bool TA, bool TB>
__global__ __launch_bounds__(256, 2)
void sgemm_kernel(const float* __restrict__ A, const float* __restrict__ B,
                  float* __restrict__ C, int K, int lda, int ldb, int ldc,
                  size_t sA, size_t sB, size_t sC)
{
    __shared__ float As[8][132];
    __shared__ float Bs[8][132];

    A += (size_t)blockIdx.z * sA;
    B += (size_t)blockIdx.z * sB;
    C += (size_t)blockIdx.z * sC;

    const int i0 = blockIdx.y * 128;
    const int j0 = blockIdx.x * 128;
    const int tid = threadIdx.x;
    const int tx = tid & 15;   // col group
    const int ty = tid >> 4;   // row group

    // acc[m][n] packs output pair (col even, col odd)
    unsigned long long acc[8][4];
#pragma unroll
    for (int m = 0; m < 8; ++m)
#pragma unroll
        for (int n = 0; n < 4; ++n) acc[m][n] = 0ull;

    for (int k0 = 0; k0 < K; k0 += 8) {
        // ---- load A tile (128 rows x 8 k) into As[k][row] ----
        if (!TA) {
            const int row = tid >> 1;
            const int kq  = (tid & 1) * 4;
            float4 av = *reinterpret_cast<const float4*>(
                A + (size_t)(i0 + row) * lda + k0 + kq);
            As[kq + 0][row] = av.x;
            As[kq + 1][row] = av.y;
            As[kq + 2][row] = av.z;
            As[kq + 3][row] = av.w;
        } else {
            const int kk = tid >> 5;
            const int ii = (tid & 31) * 4;
            *reinterpret_cast<float4*>(&As[kk][ii]) =
                *reinterpret_cast<const float4*>(
                    A + (size_t)(k0 + kk) * lda + i0 + ii);
        }
        // ---- load B tile (8 k x 128 cols) into Bs[k][col] ----
        if (!TB) {
            const int kk = tid >> 5;
            const int jj = (tid & 31) * 4;
            *reinterpret_cast<float4*>(&Bs[kk][jj]) =
                *reinterpret_cast<const float4*>(
                    B + (size_t)(k0 + kk) * ldb + j0 + jj);
        } else {
            const int col = tid >> 1;
            const int kq  = (tid & 1) * 4;
            float4 bv = *reinterpret_cast<const float4*>(
                B + (size_t)(j0 + col) * ldb + k0 + kq);
            Bs[kq + 0][col] = bv.x;
            Bs[kq + 1][col] = bv.y;
            Bs[kq + 2][col] = bv.z;
            Bs[kq + 3][col] = bv.w;
        }
        __syncthreads();

#pragma unroll
        for (int kk = 0; kk < 8; ++kk) {
            float4 a0 = *reinterpret_cast<const float4*>(&As[kk][ty * 4]);
            float4 a1 = *reinterpret_cast<const float4*>(&As[kk][64 + ty * 4]);
            ulonglong2 b0 = *reinterpret_cast<const ulonglong2*>(&Bs[kk][tx * 4]);
            ulonglong2 b1 = *reinterpret_cast<const ulonglong2*>(&Bs[kk][64 + tx * 4]);
            float a[8] = {a0.x, a0.y, a0.z, a0.w, a1.x, a1.y, a1.z, a1.w};
            unsigned long long bp[4] = {b0.x, b0.y, b1.x, b1.y};
#pragma unroll
            for (int m = 0; m < 8; ++m) {
                unsigned long long am = splat2(a[m]);
#pragma unroll
                for (int n = 0; n < 4; ++n)
                    acc[m][n] = ffma2(am, bp[n], acc[m][n]);
            }
        }
        __syncthreads();
    }

    // ---- epilogue: pairs are contiguous columns -> 8-byte stores ----
#pragma unroll
    for (int m = 0; m < 8; ++m) {
        const int gi = i0 + ((m < 4) ? (ty * 4 + m) : (64 + ty * 4 + (m - 4)));
#pragma unroll
        for (int n = 0; n < 4; ++n) {
            const int gj = j0 + ((n < 2) ? (tx * 4 + 2 * n)
                                         : (64 + tx * 4 + 2 * (n - 2)));
            *reinterpret_cast<unsigned long long*>(
                C + (size_t)gi * ldc + gj) = acc[m][n];
        }
    }
}

// ---------------------------------------------------------------------------
// Per-head LayerNorm over 32-element blocks, in place.
// One block per row, one warp per head.
// ---------------------------------------------------------------------------
__global__ __launch_bounds__(256)
void ln_heads_kernel(float* __restrict__ x)
{
    const size_t row = blockIdx.x;
    const int h = threadIdx.x >> 5;
    const int d = threadIdx.x & 31;
    float* p = x + row * 256 + h * 32;

    float v = p[d];
    float s = v;
#pragma unroll
    for (int o = 16; o > 0; o >>= 1) s += __shfl_xor_sync(0xffffffffu, s, o);
    const float mu = s * (1.0f / 32.0f);
    const float c = v - mu;
    float s2 = c * c;
#pragma unroll
    for (int o = 16; o > 0; o >>= 1) s2 += __shfl_xor_sync(0xffffffffu, s2, o);
    const float var = s2 * (1.0f / 32.0f);
    p[d] = c * rsqrtf(var + 1e-5f);
}

// ---------------------------------------------------------------------------
// Sparse attention: per (batch, row, head) warp.
//   scores_j = <q[row], k[idx[row][j]]> / sqrt(32);  softmax over 16;
//   out[row] = sum_j w_j * v[idx[row][j]]
// All tensors (B, R, 256) with head = 32-col block. 256 threads = 8 heads.
// ---------------------------------------------------------------------------
__global__ __launch_bounds__(256)
void sparse_attn_kernel(const float* __restrict__ q, const float* __restrict__ k,
                        const float* __restrict__ v, const int* __restrict__ idx,
                        float* __restrict__ out, int R)
{
    const int row = blockIdx.x;
    const size_t base = (size_t)blockIdx.y * (size_t)R * 256u;
    const int h = threadIdx.x >> 5;
    const int d = threadIdx.x & 31;
    const int col = h * 32 + d;

    const float qd = q[base + (size_t)row * 256 + col];

    int   g[16];
    float s[16];
#pragma unroll
    for (int j = 0; j < 16; ++j) {
        g[j] = __ldg(&idx[row * 16 + j]);
        const float kd = k[base + (size_t)g[j] * 256 + col];
        float p = qd * kd;
#pragma unroll
        for (int o = 16; o > 0; o >>= 1) p += __shfl_xor_sync(0xffffffffu, p, o);
        s[j] = p * 0.17677669529663687f;   // 1/sqrt(32)
    }

    float mx = s[0];
#pragma unroll
    for (int j = 1; j < 16; ++j) mx = fmaxf(mx, s[j]);
    float den = 0.0f;
#pragma unroll
    for (int j = 0; j < 16; ++j) { s[j] = expf(s[j] - mx); den += s[j]; }
    const float inv = 1.0f / den;

    float o = 0.0f;
#pragma unroll
    for (int j = 0; j < 16; ++j)
        o += s[j] * v[base + (size_t)g[j] * 256 + col];

    out[base + (size_t)row * 256 + col] = o * inv;
}

// ---------------------------------------------------------------------------
// Host launcher — graph-capturable: kernel launches only, default stream.
// Input order (metadata): x_v, x_e, d_0, W_vQ, W_vK, W_vV, W_eQ, W_eK,
//                         v_idx, e_idx. Output: float32 (B, N, 256).
// ---------------------------------------------------------------------------
extern "C" void kernel_launch(void* const* d_in, const int* in_sizes, int n_in,
                              void* d_out, int out_size)
{
    (void)in_sizes; (void)n_in; (void)out_size;
    const float* x_v  = (const float*)d_in[0];
    const float* x_e  = (const float*)d_in[1];
    const float* d0   = (const float*)d_in[2];
    const float* W_vQ = (const float*)d_in[3];
    const float* W_vK = (const float*)d_in[4];
    const float* W_vV = (const float*)d_in[5];
    const float* W_eQ = (const float*)d_in[6];
    const float* W_eK = (const float*)d_in[7];
    const int*   v_idx = (const int*)d_in[8];
    const int*   e_idx = (const int*)d_in[9];
    float* out = (float*)d_out;

    float* S = nullptr;
    cudaGetSymbolAddress((void**)&S, g_scratch);
    float* vQ = S + OFF_VQ;
    float* vK = S + OFF_VK;
    float* vV = S + OFF_VV;
    float* eQ = S + OFF_EQ;
    float* eK = S + OFF_EK;
    float* y1 = S + OFF_Y1;
    float* y2 = S + OFF_Y2;
    float* z1 = S + OFF_Z1;

    const dim3 blk(256);

    // 1) projections: C = X @ W^T  (batch folded into rows)
    {
        dim3 gv(D_SZ / 128, (B_SZ * N_SZ) / 128, 1);
        sgemm_kernel<false, true><<<gv, blk>>>(x_v, W_vQ, vQ, 256, 256, 256, 256, 0, 0, 0);
        sgemm_kernel<false, true><<<gv, blk>>>(x_v, W_vK, vK, 256, 256, 256, 256, 0, 0, 0);
        sgemm_kernel<false, true><<<gv, blk>>>(x_v, W_vV, vV, 256, 256, 256, 256, 0, 0, 0);
        dim3 ge(D_SZ / 128, (B_SZ * M_SZ) / 128, 1);
        sgemm_kernel<false, true><<<ge, blk>>>(x_e, W_eQ, eQ, 256, 256, 256, 256, 0, 0, 0);
        sgemm_kernel<false, true><<<ge, blk>>>(x_e, W_eK, eK, 256, 256, 256, 256, 0, 0, 0);
    }

    // 2) per-head LayerNorm (in place)
    ln_heads_kernel<<<B_SZ * N_SZ, blk>>>(vQ);
    ln_heads_kernel<<<B_SZ * N_SZ, blk>>>(vK);
    ln_heads_kernel<<<B_SZ * M_SZ, blk>>>(eQ);
    ln_heads_kernel<<<B_SZ * M_SZ, blk>>>(eK);

    // 3) y1[b] = d0[b] (MxN) @ vV[b] (Nx256)
    {
        dim3 g1(D_SZ / 128, M_SZ / 128, B_SZ);
        sgemm_kernel<false, false><<<g1, blk>>>(
            d0, vV, y1, N_SZ, N_SZ, 256, 256,
            (size_t)M_SZ * N_SZ, (size_t)N_SZ * 256, (size_t)M_SZ * 256);
    }

    // 4) edge sparse attention: q=eQ, k=eK, values=y1, idx=e_idx -> y2
    sparse_attn_kernel<<<dim3(M_SZ, B_SZ), blk>>>(eQ, eK, y1, e_idx, y2, M_SZ);

    // 5) z1[b] = d0[b]^T (NxM) @ y2[b] (Mx256)
    {
        dim3 g2(D_SZ / 128, N_SZ / 128, B_SZ);
        sgemm_kernel<true, false><<<g2, blk>>>(
            d0, y2, z1, M_SZ, N_SZ, 256, 256,
            (size_t)M_SZ * N_SZ, (size_t)M_SZ * 256, (size_t)N_SZ * 256);
    }

    // 6) vertex sparse attention: q=v_K, k=v_Q (note swap), values=z1 -> out
    sparse_attn_kernel<<<dim3(N_SZ, B_SZ), blk>>>(vK, vQ, z1, v_idx, out, N_SZ);
}

// round 13
// speedup vs baseline: 1.4885x; 1.4885x over previous
#include <cuda_runtime.h>
#include <stdint.h>
#include <stddef.h>

// ---------------------------------------------------------------------------
// MeshMultiHeadHodgeAttentionVertices — fp32 exact implementation
//
// Shapes: B=2, N=4096, M=12288, H=8, D=256 (dk=32), KV=KE=16
// Layout convention: every activation is (batch, rows, 256) row-major with
// column c = h*32 + d  (== split_heads column block). This makes LayerNorm
// (per 32-col block), sparse attention (per 32-col block) and the final
// transpose+reshape all trivial.
//
// Pipeline:
//   1) vQ,vK,vV = x_v @ W^T   (GEMM, TB)     rows = B*N = 8192
//      eQ,eK    = x_e @ W^T   (GEMM, TB)     rows = B*M = 24576
//   2) LayerNorm(32) in-place on vQ,vK,eQ,eK
//   3) y1[b] = d0[b] @ vV[b]                 (GEMM NN, K=4096)
//   4) y2 = sparse_attn(q=eQ, k=eK, v=y1, e_idx)
//   5) z1[b] = d0[b]^T @ y2[b]               (GEMM TA, K=12288)
//   6) out = sparse_attn(q=vK, k=vQ, v=z1, v_idx)
//
// GEMM core: 128x128x8 tile, 256 threads, 8x8 per thread, accumulation via
// packed fma.rn.f32x2 (FFMA2) -> 2x the fp32 FFMA rate on sm_103a.
// ---------------------------------------------------------------------------

#define B_SZ 2
#define N_SZ 4096
#define M_SZ 12288
#define D_SZ 256

// scratch offsets (floats)
#define OFF_VQ 0ull
#define OFF_VK 2097152ull       //  B*N*256
#define OFF_VV 4194304ull
#define OFF_EQ 6291456ull       //  then B*M*256 blocks
#define OFF_EK 12582912ull
#define OFF_Y1 18874368ull
#define OFF_Y2 25165824ull
#define OFF_Z1 31457280ull
#define SCRATCH_FLOATS 33554432ull   // 128 MiB

__device__ float g_scratch[SCRATCH_FLOATS];

// ---- packed fp32x2 helpers (sm_103a FFMA2 via PTX) ------------------------
__device__ __forceinline__ unsigned long long splat2(float a) {
    unsigned int u = __float_as_uint(a);
    unsigned long long r;
    asm("mov.b64 %0, {%1, %1};" : "=l"(r) : "r"(u));
    return r;
}
__device__ __forceinline__ unsigned long long ffma2(unsigned long long a,
                                                    unsigned long long b,
                                                    unsigned long long c) {
    unsigned long long d;
    asm("fma.rn.f32x2 %0, %1, %2, %3;" : "=l"(d) : "l"(a), "l"(b), "l"(c));
    return d;
}

// ---------------------------------------------------------------------------
// Tiled GEMM:  C[i,j] = sum_k Aop[i,k] * Bop[k,j]
//   TA=false: A row-major (i,k), lda = row stride
//   TA=true : A stored (k,i), lda = stride per k  (i.e. C = A^T_storage @ B)
//   TB=false: B row-major (k,j), ldb = row stride
//   TB=true : B stored (j,k), ldb = row stride    (i.e. B = W^T)
// All dims must be multiples of the tile (they are, by construction).
// ---------------------------------------------------------------------------
template <bool TA, bool TB>
__global__ __launch_bounds__(256, 2)
void sgemm_kernel(const float* __restrict__ A, const float* __restrict__ B,
                  float* __restrict__ C, int K, int lda, int ldb, int ldc,
                  size_t sA, size_t sB, size_t sC)
{
    __shared__ float As[8][132];
    __shared__ float Bs[8][132];

    A += (size_t)blockIdx.z * sA;
    B += (size_t)blockIdx.z * sB;
    C += (size_t)blockIdx.z * sC;

    const int i0 = blockIdx.y * 128;
    const int j0 = blockIdx.x * 128;
    const int tid = threadIdx.x;
    const int tx = tid & 15;   // col group
    const int ty = tid >> 4;   // row group

    // acc[m][n] packs output pair (col even, col odd)
    unsigned long long acc[8][4];
#pragma unroll
    for (int m = 0; m < 8; ++m)
#pragma unroll
        for (int n = 0; n < 4; ++n) acc[m][n] = 0ull;

    for (int k0 = 0; k0 < K; k0 += 8) {
        // ---- load A tile (128 rows x 8 k) into As[k][row] ----
        if (!TA) {
            const int row = tid >> 1;
            const int kq  = (tid & 1) * 4;
            float4 av = *reinterpret_cast<const float4*>(
                A + (size_t)(i0 + row) * lda + k0 + kq);
            As[kq + 0][row] = av.x;
            As[kq + 1][row] = av.y;
            As[kq + 2][row] = av.z;
            As[kq + 3][row] = av.w;
        } else {
            const int kk = tid >> 5;
            const int ii = (tid & 31) * 4;
            *reinterpret_cast<float4*>(&As[kk][ii]) =
                *reinterpret_cast<const float4*>(
                    A + (size_t)(k0 + kk) * lda + i0 + ii);
        }
        // ---- load B tile (8 k x 128 cols) into Bs[k][col] ----
        if (!TB) {
            const int kk = tid >> 5;
            const int jj = (tid & 31) * 4;
            *reinterpret_cast<float4*>(&Bs[kk][jj]) =
                *reinterpret_cast<const float4*>(
                    B + (size_t)(k0 + kk) * ldb + j0 + jj);
        } else {
            const int col = tid >> 1;
            const int kq  = (tid & 1) * 4;
            float4 bv = *reinterpret_cast<const float4*>(
                B + (size_t)(j0 + col) * ldb + k0 + kq);
            Bs[kq + 0][col] = bv.x;
            Bs[kq + 1][col] = bv.y;
            Bs[kq + 2][col] = bv.z;
            Bs[kq + 3][col] = bv.w;
        }
        __syncthreads();

#pragma unroll
        for (int kk = 0; kk < 8; ++kk) {
            float4 a0 = *reinterpret_cast<const float4*>(&As[kk][ty * 4]);
            float4 a1 = *reinterpret_cast<const float4*>(&As[kk][64 + ty * 4]);
            ulonglong2 b0 = *reinterpret_cast<const ulonglong2*>(&Bs[kk][tx * 4]);
            ulonglong2 b1 = *reinterpret_cast<const ulonglong2*>(&Bs[kk][64 + tx * 4]);
            float a[8] = {a0.x, a0.y, a0.z, a0.w, a1.x, a1.y, a1.z, a1.w};
            unsigned long long bp[4] = {b0.x, b0.y, b1.x, b1.y};
#pragma unroll
            for (int m = 0; m < 8; ++m) {
                unsigned long long am = splat2(a[m]);
#pragma unroll
                for (int n = 0; n < 4; ++n)
                    acc[m][n] = ffma2(am, bp[n], acc[m][n]);
            }
        }
        __syncthreads();
    }

    // ---- epilogue: pairs are contiguous columns -> 8-byte stores ----
#pragma unroll
    for (int m = 0; m < 8; ++m) {
        const int gi = i0 + ((m < 4) ? (ty * 4 + m) : (64 + ty * 4 + (m - 4)));
#pragma unroll
        for (int n = 0; n < 4; ++n) {
            const int gj = j0 + ((n < 2) ? (tx * 4 + 2 * n)
                                         : (64 + tx * 4 + 2 * (n - 2)));
            *reinterpret_cast<unsigned long long*>(
                C + (size_t)gi * ldc + gj) = acc[m][n];
        }
    }
}

// ---------------------------------------------------------------------------
// Per-head LayerNorm over 32-element blocks, in place.
// One block per row, one warp per head.
// ---------------------------------------------------------------------------
__global__ __launch_bounds__(256)
void ln_heads_kernel(float* __restrict__ x)
{
    const size_t row = blockIdx.x;
    const int h = threadIdx.x >> 5;
    const int d = threadIdx.x & 31;
    float* p = x + row * 256 + h * 32;

    float v = p[d];
    float s = v;
#pragma unroll
    for (int o = 16; o > 0; o >>= 1) s += __shfl_xor_sync(0xffffffffu, s, o);
    const float mu = s * (1.0f / 32.0f);
    const float c = v - mu;
    float s2 = c * c;
#pragma unroll
    for (int o = 16; o > 0; o >>= 1) s2 += __shfl_xor_sync(0xffffffffu, s2, o);
    const float var = s2 * (1.0f / 32.0f);
    p[d] = c * rsqrtf(var + 1e-5f);
}

// ---------------------------------------------------------------------------
// Sparse attention: per (batch, row, head) warp.
//   scores_j = <q[row], k[idx[row][j]]> / sqrt(32);  softmax over 16;
//   out[row] = sum_j w_j * v[idx[row][j]]
// All tensors (B, R, 256) with head = 32-col block. 256 threads = 8 heads.
// ---------------------------------------------------------------------------
__global__ __launch_bounds__(256)
void sparse_attn_kernel(const float* __restrict__ q, const float* __restrict__ k,
                        const float* __restrict__ v, const int* __restrict__ idx,
                        float* __restrict__ out, int R)
{
    const int row = blockIdx.x;
    const size_t base = (size_t)blockIdx.y * (size_t)R * 256u;
    const int h = threadIdx.x >> 5;
    const int d = threadIdx.x & 31;
    const int col = h * 32 + d;

    const float qd = q[base + (size_t)row * 256 + col];

    int   g[16];
    float s[16];
#pragma unroll
    for (int j = 0; j < 16; ++j) {
        g[j] = __ldg(&idx[row * 16 + j]);
        const float kd = k[base + (size_t)g[j] * 256 + col];
        float p = qd * kd;
#pragma unroll
        for (int o = 16; o > 0; o >>= 1) p += __shfl_xor_sync(0xffffffffu, p, o);
        s[j] = p * 0.17677669529663687f;   // 1/sqrt(32)
    }

    float mx = s[0];
#pragma unroll
    for (int j = 1; j < 16; ++j) mx = fmaxf(mx, s[j]);
    float den = 0.0f;
#pragma unroll
    for (int j = 0; j < 16; ++j) { s[j] = expf(s[j] - mx); den += s[j]; }
    const float inv = 1.0f / den;

    float o = 0.0f;
#pragma unroll
    for (int j = 0; j < 16; ++j)
        o += s[j] * v[base + (size_t)g[j] * 256 + col];

    out[base + (size_t)row * 256 + col] = o * inv;
}

// ---------------------------------------------------------------------------
// Host launcher — graph-capturable: kernel launches only, default stream.
// Input order (metadata): x_v, x_e, d_0, W_vQ, W_vK, W_vV, W_eQ, W_eK,
//                         v_idx, e_idx. Output: float32 (B, N, 256).
// ---------------------------------------------------------------------------
extern "C" void kernel_launch(void* const* d_in, const int* in_sizes, int n_in,
                              void* d_out, int out_size)
{
    (void)in_sizes; (void)n_in; (void)out_size;
    const float* x_v  = (const float*)d_in[0];
    const float* x_e  = (const float*)d_in[1];
    const float* d0   = (const float*)d_in[2];
    const float* W_vQ = (const float*)d_in[3];
    const float* W_vK = (const float*)d_in[4];
    const float* W_vV = (const float*)d_in[5];
    const float* W_eQ = (const float*)d_in[6];
    const float* W_eK = (const float*)d_in[7];
    const int*   v_idx = (const int*)d_in[8];
    const int*   e_idx = (const int*)d_in[9];
    float* out = (float*)d_out;

    float* S = nullptr;
    cudaGetSymbolAddress((void**)&S, g_scratch);
    float* vQ = S + OFF_VQ;
    float* vK = S + OFF_VK;
    float* vV = S + OFF_VV;
    float* eQ = S + OFF_EQ;
    float* eK = S + OFF_EK;
    float* y1 = S + OFF_Y1;
    float* y2 = S + OFF_Y2;
    float* z1 = S + OFF_Z1;

    const dim3 blk(256);

    // 1) projections: C = X @ W^T  (batch folded into rows)
    {
        dim3 gv(D_SZ / 128, (B_SZ * N_SZ) / 128, 1);
        sgemm_kernel<false, true><<<gv, blk>>>(x_v, W_vQ, vQ, 256, 256, 256, 256, 0, 0, 0);
        sgemm_kernel<false, true><<<gv, blk>>>(x_v, W_vK, vK, 256, 256, 256, 256, 0, 0, 0);
        sgemm_kernel<false, true><<<gv, blk>>>(x_v, W_vV, vV, 256, 256, 256, 256, 0, 0, 0);
        dim3 ge(D_SZ / 128, (B_SZ * M_SZ) / 128, 1);
        sgemm_kernel<false, true><<<ge, blk>>>(x_e, W_eQ, eQ, 256, 256, 256, 256, 0, 0, 0);
        sgemm_kernel<false, true><<<ge, blk>>>(x_e, W_eK, eK, 256, 256, 256, 256, 0, 0, 0);
    }

    // 2) per-head LayerNorm (in place)
    ln_heads_kernel<<<B_SZ * N_SZ, blk>>>(vQ);
    ln_heads_kernel<<<B_SZ * N_SZ, blk>>>(vK);
    ln_heads_kernel<<<B_SZ * M_SZ, blk>>>(eQ);
    ln_heads_kernel<<<B_SZ * M_SZ, blk>>>(eK);

    // 3) y1[b] = d0[b] (MxN) @ vV[b] (Nx256)
    {
        dim3 g1(D_SZ / 128, M_SZ / 128, B_SZ);
        sgemm_kernel<false, false><<<g1, blk>>>(
            d0, vV, y1, N_SZ, N_SZ, 256, 256,
            (size_t)M_SZ * N_SZ, (size_t)N_SZ * 256, (size_t)M_SZ * 256);
    }

    // 4) edge sparse attention: q=eQ, k=eK, values=y1, idx=e_idx -> y2
    sparse_attn_kernel<<<dim3(M_SZ, B_SZ), blk>>>(eQ, eK, y1, e_idx, y2, M_SZ);

    // 5) z1[b] = d0[b]^T (NxM) @ y2[b] (Mx256)
    {
        dim3 g2(D_SZ / 128, N_SZ / 128, B_SZ);
        sgemm_kernel<true, false><<<g2, blk>>>(
            d0, y2, z1, M_SZ, N_SZ, 256, 256,
            (size_t)M_SZ * N_SZ, (size_t)M_SZ * 256, (size_t)N_SZ * 256);
    }

    // 6) vertex sparse attention: q=v_K, k=v_Q (note swap), values=z1 -> out
    sparse_attn_kernel<<<dim3(N_SZ, B_SZ), blk>>>(vK, vQ, z1, v_idx, out, N_SZ);
}